// round 14
// baseline (speedup 1.0000x reference)
#include <cuda_runtime.h>
#include <math.h>
#include <stdint.h>

#define ND 4096
#define NM 8192
#define NN 12288           // ND + NM
#define NE 262144
#define KNN_K 50
#define TILE_KNN 1024

// ---------------- scratch (static __device__, no allocations) ----------------
__device__ float g_h1[(size_t)NN * 2048];     // GAT1 per-head features
__device__ float g_g1[(size_t)NN * 2048];     // relu(GAT1 out + b)
__device__ float g_h2[(size_t)NN * 256];      // GAT2 features
__device__ float g_cat1[(size_t)NN * 1024];   // [x1(256) | x2(256) | simLN(512)]
__device__ float g_cat2[(size_t)NN * 128];    // [h(64) | feats(64)]
__device__ float g_hh[(size_t)NN * 64];       // elu(fc1) output
__device__ float g_ebuf1[(size_t)NE * 8];     // GAT1 edge scores -> exp values
__device__ float g_ebuf2[NE];                 // GAT2 edge scores -> exp values
__device__ float g_asrc1[NN * 8], g_adst1[NN * 8];
__device__ float g_m1[NN * 8], g_den1[NN * 8], g_inv1[NN * 8];
__device__ float g_as2[NN], g_ad2[NN], g_m2[NN], g_den2[NN], g_inv2[NN];
__device__ float4 g_g4[NN];                   // 4-D projection for KNN
__device__ float g_sq[NN];
__device__ int   g_knn[NN * KNN_K];
__device__ int   g_deg[NN], g_rowstart[NN + 1], g_cursor[NN], g_csr[NE];
__device__ float g_pd[NN], g_pm[NN];

// ---------------- generic tiled SGEMM: C = act(A@B + bias) ----------------
// A row-major [M,K] with leading dim lda; B row-major [K,Nc] ld ldb; C ld ldc.
// act: 0 none, 1 relu, 2 elu. K must be a multiple of 16 (all call sites are).
__global__ __launch_bounds__(256) void sgemm_kernel(
    const float* __restrict__ A, int lda,
    const float* __restrict__ B, int ldb,
    float* __restrict__ C, int ldc,
    int M, int K, int Nc,
    const float* __restrict__ bias, int act)
{
    __shared__ float As[16][132];   // [k][m], padded
    __shared__ float Bs[16][68];    // [k][n], padded
    int bm = blockIdx.y * 128, bn = blockIdx.x * 64;
    int tid = threadIdx.x;
    int ty = tid >> 4, tx = tid & 15;
    float acc[8][4];
#pragma unroll
    for (int i = 0; i < 8; i++)
#pragma unroll
        for (int j = 0; j < 4; j++) acc[i][j] = 0.f;

    for (int k0 = 0; k0 < K; k0 += 16) {
#pragma unroll
        for (int i = 0; i < 8; i++) {
            int idx = tid + i * 256;
            int m = idx >> 4, kk = idx & 15;
            int gm = bm + m;
            As[kk][m] = (gm < M) ? A[(size_t)gm * lda + k0 + kk] : 0.f;
        }
#pragma unroll
        for (int i = 0; i < 4; i++) {
            int idx = tid + i * 256;
            int kk = idx >> 6, n = idx & 63;
            int gn = bn + n;
            Bs[kk][n] = (gn < Nc) ? B[(size_t)(k0 + kk) * ldb + gn] : 0.f;
        }
        __syncthreads();
#pragma unroll
        for (int kk = 0; kk < 16; kk++) {
            float4 a0 = *(const float4*)&As[kk][ty * 8];
            float4 a1 = *(const float4*)&As[kk][ty * 8 + 4];
            float4 b4 = *(const float4*)&Bs[kk][tx * 4];
            float av[8] = {a0.x, a0.y, a0.z, a0.w, a1.x, a1.y, a1.z, a1.w};
            float bv[4] = {b4.x, b4.y, b4.z, b4.w};
#pragma unroll
            for (int i = 0; i < 8; i++)
#pragma unroll
                for (int j = 0; j < 4; j++) acc[i][j] += av[i] * bv[j];
        }
        __syncthreads();
    }
#pragma unroll
    for (int i = 0; i < 8; i++) {
        int gm = bm + ty * 8 + i;
        if (gm >= M) continue;
#pragma unroll
        for (int j = 0; j < 4; j++) {
            int gn = bn + tx * 4 + j;
            if (gn >= Nc) continue;
            float v = acc[i][j];
            if (bias) v += bias[gn];
            if (act == 1) v = fmaxf(v, 0.f);
            else if (act == 2) v = (v > 0.f) ? v : expm1f(v);
            C[(size_t)gm * ldc + gn] = v;
        }
    }
}

// ---------------- init ----------------
__global__ void init_kernel()
{
    int i = blockIdx.x * blockDim.x + threadIdx.x;
    if (i < NN * 8) { g_m1[i] = -INFINITY; g_den1[i] = 0.f; }
    if (i < NN)     { g_m2[i] = -INFINITY; g_den2[i] = 0.f; g_deg[i] = 0; g_cursor[i] = 0; }
}

// ---------------- CSR build over dst ----------------
__global__ void deg_kernel(const int* __restrict__ dst)
{
    int e = blockIdx.x * blockDim.x + threadIdx.x;
    if (e < NE) atomicAdd(&g_deg[dst[e]], 1);
}

__global__ __launch_bounds__(1024) void scan_kernel()
{
    __shared__ int ps[1024];
    int t = threadIdx.x;
    int base = t * 12;
    int loc[12]; int s = 0;
#pragma unroll
    for (int i = 0; i < 12; i++) { int v = g_deg[base + i]; loc[i] = s; s += v; }
    ps[t] = s;
    __syncthreads();
    for (int off = 1; off < 1024; off <<= 1) {
        int v = ps[t];
        int add = (t >= off) ? ps[t - off] : 0;
        __syncthreads();
        ps[t] = v + add;
        __syncthreads();
    }
    int prev = (t == 0) ? 0 : ps[t - 1];
#pragma unroll
    for (int i = 0; i < 12; i++) g_rowstart[base + i] = prev + loc[i];
    if (t == 1023) g_rowstart[NN] = ps[1023];
}

__global__ void scatter_kernel(const int* __restrict__ dst)
{
    int e = blockIdx.x * blockDim.x + threadIdx.x;
    if (e >= NE) return;
    int d = dst[e];
    int p = atomicAdd(&g_cursor[d], 1);
    g_csr[g_rowstart[d] + p] = e;
}

// ---------------- attention node scores ----------------
__global__ __launch_bounds__(256) void attn_node1_kernel(
    const float* __restrict__ att_src, const float* __restrict__ att_dst)
{
    int n = blockIdx.x;
    int t = threadIdx.x, w = t >> 5, l = t & 31;
    const float* hp = g_h1 + (size_t)n * 2048 + w * 256;
    const float* as = att_src + w * 256;
    const float* ad = att_dst + w * 256;
    float s = 0.f, d = 0.f;
    for (int c = l; c < 256; c += 32) { float v = hp[c]; s += v * as[c]; d += v * ad[c]; }
#pragma unroll
    for (int off = 16; off; off >>= 1) {
        s += __shfl_down_sync(0xffffffffu, s, off);
        d += __shfl_down_sync(0xffffffffu, d, off);
    }
    if (l == 0) { g_asrc1[n * 8 + w] = s; g_adst1[n * 8 + w] = d; }
}

__global__ __launch_bounds__(256) void attn_node2_kernel(
    const float* __restrict__ att_src, const float* __restrict__ att_dst)
{
    __shared__ float ss[256], sd[256];
    int n = blockIdx.x, t = threadIdx.x;
    float v = g_h2[(size_t)n * 256 + t];
    ss[t] = v * att_src[t];
    sd[t] = v * att_dst[t];
    __syncthreads();
    for (int s = 128; s; s >>= 1) {
        if (t < s) { ss[t] += ss[t + s]; sd[t] += sd[t + s]; }
        __syncthreads();
    }
    if (t == 0) { g_as2[n] = ss[0]; g_ad2[n] = sd[0]; }
}

// ---------------- edge softmax passes ----------------
__device__ __forceinline__ void atomicMaxF(float* addr, float val)
{
    int* ia = (int*)addr;
    int old = *ia;
    while (__int_as_float(old) < val) {
        int assumed = old;
        old = atomicCAS(ia, assumed, __float_as_int(val));
        if (old == assumed) break;
    }
}

__global__ void edge1_pass1(const int* __restrict__ src, const int* __restrict__ dst)
{
    int e = blockIdx.x * blockDim.x + threadIdx.x;
    if (e >= NE) return;
    int s = src[e], d = dst[e];
#pragma unroll
    for (int h = 0; h < 8; h++) {
        float v = g_asrc1[s * 8 + h] + g_adst1[d * 8 + h];
        v = (v >= 0.f) ? v : 0.2f * v;
        g_ebuf1[(size_t)e * 8 + h] = v;
        atomicMaxF(&g_m1[d * 8 + h], v);
    }
}

__global__ void edge1_pass2(const int* __restrict__ dst)
{
    int e = blockIdx.x * blockDim.x + threadIdx.x;
    if (e >= NE) return;
    int d = dst[e];
#pragma unroll
    for (int h = 0; h < 8; h++) {
        float m = g_m1[d * 8 + h];
        if (!isfinite(m)) m = 0.f;
        float ex = expf(g_ebuf1[(size_t)e * 8 + h] - m);
        g_ebuf1[(size_t)e * 8 + h] = ex;
        atomicAdd(&g_den1[d * 8 + h], ex);
    }
}

__global__ void edge2_pass1(const int* __restrict__ src, const int* __restrict__ dst)
{
    int e = blockIdx.x * blockDim.x + threadIdx.x;
    if (e >= NE) return;
    float v = g_as2[src[e]] + g_ad2[dst[e]];
    v = (v >= 0.f) ? v : 0.2f * v;
    g_ebuf2[e] = v;
    atomicMaxF(&g_m2[dst[e]], v);
}

__global__ void edge2_pass2(const int* __restrict__ dst)
{
    int e = blockIdx.x * blockDim.x + threadIdx.x;
    if (e >= NE) return;
    int d = dst[e];
    float m = g_m2[d];
    if (!isfinite(m)) m = 0.f;
    float ex = expf(g_ebuf2[e] - m);
    g_ebuf2[e] = ex;
    atomicAdd(&g_den2[d], ex);
}

__global__ void invden_kernel(const float* __restrict__ den, float* __restrict__ inv, int count)
{
    int i = blockIdx.x * blockDim.x + threadIdx.x;
    if (i < count) inv[i] = 1.f / fmaxf(den[i], 1e-16f);
}

// ---------------- GAT aggregations (CSR, no atomics) ----------------
__global__ __launch_bounds__(256) void agg1_kernel(const int* __restrict__ src,
                                                   const float* __restrict__ bias)
{
    int n = blockIdx.x, t = threadIdx.x;
    __shared__ float sinv[8];
    if (t < 8) sinv[t] = g_inv1[n * 8 + t];
    __syncthreads();
    float acc[8];
#pragma unroll
    for (int k = 0; k < 8; k++) acc[k] = 0.f;
    int s0 = g_rowstart[n], s1 = g_rowstart[n + 1];
    for (int ii = s0; ii < s1; ii++) {
        int e = g_csr[ii];
        int sNode = src[e];
        const float* hp = g_h1 + (size_t)sNode * 2048 + t;
        const float4* ap = (const float4*)(g_ebuf1 + (size_t)e * 8);
        float4 a0 = ap[0], a1 = ap[1];
        acc[0] += a0.x * hp[0];
        acc[1] += a0.y * hp[256];
        acc[2] += a0.z * hp[512];
        acc[3] += a0.w * hp[768];
        acc[4] += a1.x * hp[1024];
        acc[5] += a1.y * hp[1280];
        acc[6] += a1.z * hp[1536];
        acc[7] += a1.w * hp[1792];
    }
#pragma unroll
    for (int k = 0; k < 8; k++) {
        float v = acc[k] * sinv[k] + bias[k * 256 + t];
        g_g1[(size_t)n * 2048 + k * 256 + t] = fmaxf(v, 0.f);   // relu(g1)
    }
}

__global__ __launch_bounds__(256) void agg2_kernel(const int* __restrict__ src,
                                                   const float* __restrict__ bias)
{
    int n = blockIdx.x, t = threadIdx.x;
    float inv = g_inv2[n];
    float acc = 0.f;
    int s0 = g_rowstart[n], s1 = g_rowstart[n + 1];
    for (int ii = s0; ii < s1; ii++) {
        int e = g_csr[ii];
        acc += g_ebuf2[e] * g_h2[(size_t)src[e] * 256 + t];
    }
    // x2 -> cat1 cols [256,512)
    g_cat1[(size_t)n * 1024 + 256 + t] = acc * inv + bias[t];
}

// ---------------- projection to 4-D + squared norms ----------------
__global__ __launch_bounds__(256) void proj_kernel(const float* __restrict__ W_proj,
                                                   const float* __restrict__ b_proj)
{
    int gw = (blockIdx.x * 256 + threadIdx.x) >> 5;
    int l = threadIdx.x & 31;
    if (gw >= NN) return;
    const float* f = g_cat1 + (size_t)gw * 1024;
    float a0 = 0.f, a1 = 0.f, a2 = 0.f, a3 = 0.f;
    for (int j = l; j < 512; j += 32) {
        float v = f[j];
        float4 w = ((const float4*)W_proj)[j];
        a0 += v * w.x; a1 += v * w.y; a2 += v * w.z; a3 += v * w.w;
    }
#pragma unroll
    for (int off = 16; off; off >>= 1) {
        a0 += __shfl_down_sync(0xffffffffu, a0, off);
        a1 += __shfl_down_sync(0xffffffffu, a1, off);
        a2 += __shfl_down_sync(0xffffffffu, a2, off);
        a3 += __shfl_down_sync(0xffffffffu, a3, off);
    }
    if (l == 0) {
        a0 += b_proj[0]; a1 += b_proj[1]; a2 += b_proj[2]; a3 += b_proj[3];
        g_g4[gw] = make_float4(a0, a1, a2, a3);
        g_sq[gw] = a0 * a0 + a1 * a1 + a2 * a2 + a3 * a3;
    }
}

// ---------------- exact KNN (brute force, top-50) ----------------
__global__ __launch_bounds__(128) void knn_kernel()
{
    __shared__ float4 sg[TILE_KNN];
    __shared__ float ssq[TILE_KNN];
    int row = blockIdx.x * 128 + threadIdx.x;
    float4 gi = g_g4[row];
    float sqi = g_sq[row];
    float bd[KNN_K];
    int bi[KNN_K];
#pragma unroll
    for (int i = 0; i < KNN_K; i++) { bd[i] = INFINITY; bi[i] = -1; }
    float worst = INFINITY;
    for (int t0 = 0; t0 < NN; t0 += TILE_KNN) {
        __syncthreads();
        for (int i = threadIdx.x; i < TILE_KNN; i += 128) {
            sg[i] = g_g4[t0 + i];
            ssq[i] = g_sq[t0 + i];
        }
        __syncthreads();
        for (int j = 0; j < TILE_KNN; j++) {
            float4 gj = sg[j];
            float dot = gi.x * gj.x + gi.y * gj.y + gi.z * gj.z + gi.w * gj.w;
            float d2 = sqi + ssq[j] - 2.f * dot;
            if (d2 < worst) {                 // strict < : lower index kept on ties
                int p = KNN_K - 1;
                while (p > 0 && bd[p - 1] > d2) {
                    bd[p] = bd[p - 1];
                    bi[p] = bi[p - 1];
                    p--;
                }
                bd[p] = d2;
                bi[p] = t0 + j;
                worst = bd[KNN_K - 1];
            }
        }
    }
    for (int i = 0; i < KNN_K; i++) g_knn[row * KNN_K + i] = bi[i];
}

// ---------------- sim = mean(final[idx]) -> LayerNorm -> cat1[512:1024) ----------------
__global__ __launch_bounds__(256) void simln_kernel(const float* __restrict__ ln_g,
                                                    const float* __restrict__ ln_b)
{
    __shared__ float red[256];
    int n = blockIdx.x, t = threadIdx.x;
    const int* ip = g_knn + n * KNN_K;
    float a0 = 0.f, a1 = 0.f;
    for (int kk = 0; kk < KNN_K; kk++) {
        const float* r = g_cat1 + (size_t)ip[kk] * 1024;
        a0 += r[t];
        a1 += r[t + 256];
    }
    a0 *= (1.f / 50.f);
    a1 *= (1.f / 50.f);
    red[t] = a0 + a1;
    __syncthreads();
    for (int s = 128; s; s >>= 1) { if (t < s) red[t] += red[t + s]; __syncthreads(); }
    float mu = red[0] * (1.f / 512.f);
    __syncthreads();
    float d0 = a0 - mu, d1 = a1 - mu;
    red[t] = d0 * d0 + d1 * d1;
    __syncthreads();
    for (int s = 128; s; s >>= 1) { if (t < s) red[t] += red[t + s]; __syncthreads(); }
    float var = red[0] * (1.f / 512.f);
    float rstd = rsqrtf(var + 1e-5f);
    float* o = g_cat1 + (size_t)n * 1024 + 512;
    o[t]       = d0 * rstd * ln_g[t]       + ln_b[t];
    o[t + 256] = d1 * rstd * ln_g[t + 256] + ln_b[t + 256];
}

// ---------------- final edge prediction ----------------
__global__ __launch_bounds__(256) void pred_node_kernel(const float* __restrict__ W_pred)
{
    int gw = (blockIdx.x * 256 + threadIdx.x) >> 5;
    int l = threadIdx.x & 31;
    if (gw >= NN) return;
    const float* hp = g_hh + (size_t)gw * 64;
    float a = 0.f, b = 0.f;
    for (int c = l; c < 64; c += 32) {
        float v = hp[c];
        a += v * W_pred[c];
        b += v * W_pred[64 + c];
    }
#pragma unroll
    for (int off = 16; off; off >>= 1) {
        a += __shfl_down_sync(0xffffffffu, a, off);
        b += __shfl_down_sync(0xffffffffu, b, off);
    }
    if (l == 0) { g_pd[gw] = a; g_pm[gw] = b; }
}

__global__ void pred_edge_kernel(const int* __restrict__ dis, const int* __restrict__ mir,
                                 const float* __restrict__ b_pred, float* __restrict__ out)
{
    int e = blockIdx.x * blockDim.x + threadIdx.x;
    if (e >= NE) return;
    float z = g_pd[dis[e]] + g_pm[mir[e]] + b_pred[0];
    out[e] = 1.f / (1.f + expf(-z));
}

// ---------------- host launcher ----------------
static inline void launch_sgemm(const float* A, int lda, const float* B, int ldb,
                                float* C, int ldc, int M, int K, int Nc,
                                const float* bias, int act)
{
    dim3 grid((Nc + 63) / 64, (M + 127) / 128);
    sgemm_kernel<<<grid, 256>>>(A, lda, B, ldb, C, ldc, M, K, Nc, bias, act);
}

extern "C" void kernel_launch(void* const* d_in, const int* in_sizes, int n_in,
                              void* d_out, int out_size)
{
    const float* d_sim    = (const float*)d_in[0];
    const float* m_sim    = (const float*)d_in[1];
    const int*   diseases = (const int*)d_in[2];
    const int*   mirnas   = (const int*)d_in[3];
    const float* W_dfc    = (const float*)d_in[4];
    const float* W_mfc    = (const float*)d_in[5];
    const float* W_lin1   = (const float*)d_in[6];
    const float* b_lin1   = (const float*)d_in[7];
    const float* W_gat1   = (const float*)d_in[8];
    const float* att_src1 = (const float*)d_in[9];
    const float* att_dst1 = (const float*)d_in[10];
    const float* b_gat1   = (const float*)d_in[11];
    const float* W_gat2   = (const float*)d_in[12];
    const float* att_src2 = (const float*)d_in[13];
    const float* att_dst2 = (const float*)d_in[14];
    const float* b_gat2   = (const float*)d_in[15];
    const float* W_proj   = (const float*)d_in[16];
    const float* b_proj   = (const float*)d_in[17];
    const float* ln_g     = (const float*)d_in[18];
    const float* ln_b     = (const float*)d_in[19];
    const float* W_lin    = (const float*)d_in[20];
    const float* b_lin    = (const float*)d_in[21];
    const float* W_dfc1   = (const float*)d_in[22];
    const float* b_dfc1   = (const float*)d_in[23];
    const float* W_mfc1   = (const float*)d_in[24];
    const float* b_mfc1   = (const float*)d_in[25];
    const float* W_pred   = (const float*)d_in[26];
    const float* b_pred   = (const float*)d_in[27];
    float* out = (float*)d_out;

    float *h1, *g1, *h2, *cat1, *cat2, *hh;
    cudaGetSymbolAddress((void**)&h1,   g_h1);
    cudaGetSymbolAddress((void**)&g1,   g_g1);
    cudaGetSymbolAddress((void**)&h2,   g_h2);
    cudaGetSymbolAddress((void**)&cat1, g_cat1);
    cudaGetSymbolAddress((void**)&cat2, g_cat2);
    cudaGetSymbolAddress((void**)&hh,   g_hh);

    const int EB = (NE + 255) / 256;

    // 1-2: feats -> cat2 cols [64,128)
    launch_sgemm(d_sim, ND, W_dfc, 64, cat2 + 64, 128, ND, ND, 64, nullptr, 0);
    launch_sgemm(m_sim, NM, W_mfc, 64, cat2 + (size_t)ND * 128 + 64, 128, NM, NM, 64, nullptr, 0);

    // 3: x1 = relu(feats@W_lin1 + b) -> cat1 cols [0,256)
    launch_sgemm(cat2 + 64, 128, W_lin1, 256, cat1, 1024, NN, 64, 256, b_lin1, 1);

    // 4: h1 = feats@W_gat1
    launch_sgemm(cat2 + 64, 128, W_gat1, 2048, h1, 2048, NN, 64, 2048, nullptr, 0);

    // 5: init softmax/CSR buffers
    init_kernel<<<(NN * 8 + 255) / 256, 256>>>();

    // 6-8: CSR by dst
    deg_kernel<<<EB, 256>>>(mirnas);
    scan_kernel<<<1, 1024>>>();
    scatter_kernel<<<EB, 256>>>(mirnas);

    // 9-13: GAT1
    attn_node1_kernel<<<NN, 256>>>(att_src1, att_dst1);
    edge1_pass1<<<EB, 256>>>(diseases, mirnas);
    edge1_pass2<<<EB, 256>>>(mirnas);
    invden_kernel<<<(NN * 8 + 255) / 256, 256>>>(g_den1, g_inv1, NN * 8);
    agg1_kernel<<<NN, 256>>>(diseases, b_gat1);

    // 14: h2 = g1@W_gat2 (biggest GEMM)
    launch_sgemm(g1, 2048, W_gat2, 256, h2, 256, NN, 2048, 256, nullptr, 0);

    // 15-18: GAT2 -> x2 into cat1 cols [256,512)
    attn_node2_kernel<<<NN, 256>>>(att_src2, att_dst2);
    edge2_pass1<<<EB, 256>>>(diseases, mirnas);
    edge2_pass2<<<EB, 256>>>(mirnas);
    invden_kernel<<<(NN + 255) / 256, 256>>>(g_den2, g_inv2, NN);
    agg2_kernel<<<NN, 256>>>(diseases, b_gat2);

    // 19-21: KNN + sim + LN -> cat1 cols [512,1024)
    proj_kernel<<<NN / 8, 256>>>(W_proj, b_proj);
    knn_kernel<<<NN / 128, 128>>>();
    simln_kernel<<<NN, 256>>>(ln_g, ln_b);

    // 22: h = cat1@W_lin + b -> cat2 cols [0,64)
    launch_sgemm(cat1, 1024, W_lin, 64, cat2, 128, NN, 1024, 64, b_lin, 0);

    // 23-24: elu(fc1) -> hh
    launch_sgemm(cat2, 128, W_dfc1, 64, hh, 64, ND, 128, 64, b_dfc1, 2);
    launch_sgemm(cat2 + (size_t)ND * 128, 128, W_mfc1, 64, hh + (size_t)ND * 64, 64,
                 NM, 128, 64, b_mfc1, 2);

    // 25-26: prediction
    pred_node_kernel<<<(NN * 32 + 255) / 256, 256>>>(W_pred);
    pred_edge_kernel<<<EB, 256>>>(diseases, mirnas, b_pred, out);
}

// round 15
// speedup vs baseline: 12.9718x; 12.9718x over previous
#include <cuda_runtime.h>
#include <math.h>
#include <stdint.h>

#define ND 4096
#define NM 8192
#define NN 12288           // ND + NM
#define NE 262144
#define KNN_K 50

// ---------------- scratch (static __device__, no allocations) ----------------
__device__ float g_h1[(size_t)NN * 2048];     // GAT1 per-head features
__device__ float g_g1[(size_t)NN * 2048];     // relu(GAT1 out + b)
__device__ float g_h2[(size_t)NN * 256];      // GAT2 features
__device__ float g_cat1[(size_t)NN * 1024];   // [x1(256) | x2(256) | simLN(512)]
__device__ float g_cat2[(size_t)NN * 128];    // [h(64) | feats(64)]
__device__ float g_hh[(size_t)NN * 64];       // elu(fc1) output
__device__ float g_ebuf1[(size_t)NE * 8];     // GAT1 edge scores -> exp values
__device__ float g_ebuf2[NE];                 // GAT2 edge scores -> exp values
__device__ float g_asrc1[NN * 8], g_adst1[NN * 8];
__device__ float g_m1[NN * 8], g_den1[NN * 8], g_inv1[NN * 8];
__device__ float g_as2[NN], g_ad2[NN], g_m2[NN], g_den2[NN], g_inv2[NN];
__device__ float4 g_g4[NN];                   // 4-D projection for KNN
__device__ float g_sq[NN];
__device__ int   g_knn[NN * KNN_K];
__device__ int   g_deg[NN], g_rowstart[NN + 1], g_cursor[NN], g_csr[NE];
__device__ float g_pd[NN], g_pm[NN];

// ---------------- generic tiled SGEMM: C = act(A@B + bias) ----------------
// A row-major [M,K] with leading dim lda; B row-major [K,Nc] ld ldb; C ld ldc.
// act: 0 none, 1 relu, 2 elu. K must be a multiple of 16 (all call sites are).
__global__ __launch_bounds__(256) void sgemm_kernel(
    const float* __restrict__ A, int lda,
    const float* __restrict__ B, int ldb,
    float* __restrict__ C, int ldc,
    int M, int K, int Nc,
    const float* __restrict__ bias, int act)
{
    __shared__ float As[16][132];   // [k][m], padded
    __shared__ float Bs[16][68];    // [k][n], padded
    int bm = blockIdx.y * 128, bn = blockIdx.x * 64;
    int tid = threadIdx.x;
    int ty = tid >> 4, tx = tid & 15;
    float acc[8][4];
#pragma unroll
    for (int i = 0; i < 8; i++)
#pragma unroll
        for (int j = 0; j < 4; j++) acc[i][j] = 0.f;

    for (int k0 = 0; k0 < K; k0 += 16) {
#pragma unroll
        for (int i = 0; i < 8; i++) {
            int idx = tid + i * 256;
            int m = idx >> 4, kk = idx & 15;
            int gm = bm + m;
            As[kk][m] = (gm < M) ? A[(size_t)gm * lda + k0 + kk] : 0.f;
        }
#pragma unroll
        for (int i = 0; i < 4; i++) {
            int idx = tid + i * 256;
            int kk = idx >> 6, n = idx & 63;
            int gn = bn + n;
            Bs[kk][n] = (gn < Nc) ? B[(size_t)(k0 + kk) * ldb + gn] : 0.f;
        }
        __syncthreads();
#pragma unroll
        for (int kk = 0; kk < 16; kk++) {
            float4 a0 = *(const float4*)&As[kk][ty * 8];
            float4 a1 = *(const float4*)&As[kk][ty * 8 + 4];
            float4 b4 = *(const float4*)&Bs[kk][tx * 4];
            float av[8] = {a0.x, a0.y, a0.z, a0.w, a1.x, a1.y, a1.z, a1.w};
            float bv[4] = {b4.x, b4.y, b4.z, b4.w};
#pragma unroll
            for (int i = 0; i < 8; i++)
#pragma unroll
                for (int j = 0; j < 4; j++) acc[i][j] += av[i] * bv[j];
        }
        __syncthreads();
    }
#pragma unroll
    for (int i = 0; i < 8; i++) {
        int gm = bm + ty * 8 + i;
        if (gm >= M) continue;
#pragma unroll
        for (int j = 0; j < 4; j++) {
            int gn = bn + tx * 4 + j;
            if (gn >= Nc) continue;
            float v = acc[i][j];
            if (bias) v += bias[gn];
            if (act == 1) v = fmaxf(v, 0.f);
            else if (act == 2) v = (v > 0.f) ? v : expm1f(v);
            C[(size_t)gm * ldc + gn] = v;
        }
    }
}

// ---------------- init ----------------
__global__ void init_kernel()
{
    int i = blockIdx.x * blockDim.x + threadIdx.x;
    if (i < NN * 8) { g_m1[i] = -INFINITY; g_den1[i] = 0.f; }
    if (i < NN)     { g_m2[i] = -INFINITY; g_den2[i] = 0.f; g_deg[i] = 0; g_cursor[i] = 0; }
}

// ---------------- CSR build over dst ----------------
__global__ void deg_kernel(const int* __restrict__ dst)
{
    int e = blockIdx.x * blockDim.x + threadIdx.x;
    if (e < NE) atomicAdd(&g_deg[dst[e]], 1);
}

__global__ __launch_bounds__(1024) void scan_kernel()
{
    __shared__ int ps[1024];
    int t = threadIdx.x;
    int base = t * 12;
    int loc[12]; int s = 0;
#pragma unroll
    for (int i = 0; i < 12; i++) { int v = g_deg[base + i]; loc[i] = s; s += v; }
    ps[t] = s;
    __syncthreads();
    for (int off = 1; off < 1024; off <<= 1) {
        int v = ps[t];
        int add = (t >= off) ? ps[t - off] : 0;
        __syncthreads();
        ps[t] = v + add;
        __syncthreads();
    }
    int prev = (t == 0) ? 0 : ps[t - 1];
#pragma unroll
    for (int i = 0; i < 12; i++) g_rowstart[base + i] = prev + loc[i];
    if (t == 1023) g_rowstart[NN] = ps[1023];
}

__global__ void scatter_kernel(const int* __restrict__ dst)
{
    int e = blockIdx.x * blockDim.x + threadIdx.x;
    if (e >= NE) return;
    int d = dst[e];
    int p = atomicAdd(&g_cursor[d], 1);
    g_csr[g_rowstart[d] + p] = e;
}

// ---------------- attention node scores ----------------
__global__ __launch_bounds__(256) void attn_node1_kernel(
    const float* __restrict__ att_src, const float* __restrict__ att_dst)
{
    int n = blockIdx.x;
    int t = threadIdx.x, w = t >> 5, l = t & 31;
    const float* hp = g_h1 + (size_t)n * 2048 + w * 256;
    const float* as = att_src + w * 256;
    const float* ad = att_dst + w * 256;
    float s = 0.f, d = 0.f;
    for (int c = l; c < 256; c += 32) { float v = hp[c]; s += v * as[c]; d += v * ad[c]; }
#pragma unroll
    for (int off = 16; off; off >>= 1) {
        s += __shfl_down_sync(0xffffffffu, s, off);
        d += __shfl_down_sync(0xffffffffu, d, off);
    }
    if (l == 0) { g_asrc1[n * 8 + w] = s; g_adst1[n * 8 + w] = d; }
}

__global__ __launch_bounds__(256) void attn_node2_kernel(
    const float* __restrict__ att_src, const float* __restrict__ att_dst)
{
    __shared__ float ss[256], sd[256];
    int n = blockIdx.x, t = threadIdx.x;
    float v = g_h2[(size_t)n * 256 + t];
    ss[t] = v * att_src[t];
    sd[t] = v * att_dst[t];
    __syncthreads();
    for (int s = 128; s; s >>= 1) {
        if (t < s) { ss[t] += ss[t + s]; sd[t] += sd[t + s]; }
        __syncthreads();
    }
    if (t == 0) { g_as2[n] = ss[0]; g_ad2[n] = sd[0]; }
}

// ---------------- edge softmax passes ----------------
__device__ __forceinline__ void atomicMaxF(float* addr, float val)
{
    int* ia = (int*)addr;
    int old = *ia;
    while (__int_as_float(old) < val) {
        int assumed = old;
        old = atomicCAS(ia, assumed, __float_as_int(val));
        if (old == assumed) break;
    }
}

__global__ void edge1_pass1(const int* __restrict__ src, const int* __restrict__ dst)
{
    int e = blockIdx.x * blockDim.x + threadIdx.x;
    if (e >= NE) return;
    int s = src[e], d = dst[e];
#pragma unroll
    for (int h = 0; h < 8; h++) {
        float v = g_asrc1[s * 8 + h] + g_adst1[d * 8 + h];
        v = (v >= 0.f) ? v : 0.2f * v;
        g_ebuf1[(size_t)e * 8 + h] = v;
        atomicMaxF(&g_m1[d * 8 + h], v);
    }
}

__global__ void edge1_pass2(const int* __restrict__ dst)
{
    int e = blockIdx.x * blockDim.x + threadIdx.x;
    if (e >= NE) return;
    int d = dst[e];
#pragma unroll
    for (int h = 0; h < 8; h++) {
        float m = g_m1[d * 8 + h];
        if (!isfinite(m)) m = 0.f;
        float ex = expf(g_ebuf1[(size_t)e * 8 + h] - m);
        g_ebuf1[(size_t)e * 8 + h] = ex;
        atomicAdd(&g_den1[d * 8 + h], ex);
    }
}

__global__ void edge2_pass1(const int* __restrict__ src, const int* __restrict__ dst)
{
    int e = blockIdx.x * blockDim.x + threadIdx.x;
    if (e >= NE) return;
    float v = g_as2[src[e]] + g_ad2[dst[e]];
    v = (v >= 0.f) ? v : 0.2f * v;
    g_ebuf2[e] = v;
    atomicMaxF(&g_m2[dst[e]], v);
}

__global__ void edge2_pass2(const int* __restrict__ dst)
{
    int e = blockIdx.x * blockDim.x + threadIdx.x;
    if (e >= NE) return;
    int d = dst[e];
    float m = g_m2[d];
    if (!isfinite(m)) m = 0.f;
    float ex = expf(g_ebuf2[e] - m);
    g_ebuf2[e] = ex;
    atomicAdd(&g_den2[d], ex);
}

__global__ void invden_kernel(const float* __restrict__ den, float* __restrict__ inv, int count)
{
    int i = blockIdx.x * blockDim.x + threadIdx.x;
    if (i < count) inv[i] = 1.f / fmaxf(den[i], 1e-16f);
}

// ---------------- GAT aggregations (CSR, no atomics) ----------------
__global__ __launch_bounds__(256) void agg1_kernel(const int* __restrict__ src,
                                                   const float* __restrict__ bias)
{
    int n = blockIdx.x, t = threadIdx.x;
    __shared__ float sinv[8];
    if (t < 8) sinv[t] = g_inv1[n * 8 + t];
    __syncthreads();
    float acc[8];
#pragma unroll
    for (int k = 0; k < 8; k++) acc[k] = 0.f;
    int s0 = g_rowstart[n], s1 = g_rowstart[n + 1];
    for (int ii = s0; ii < s1; ii++) {
        int e = g_csr[ii];
        int sNode = src[e];
        const float* hp = g_h1 + (size_t)sNode * 2048 + t;
        const float4* ap = (const float4*)(g_ebuf1 + (size_t)e * 8);
        float4 a0 = ap[0], a1 = ap[1];
        acc[0] += a0.x * hp[0];
        acc[1] += a0.y * hp[256];
        acc[2] += a0.z * hp[512];
        acc[3] += a0.w * hp[768];
        acc[4] += a1.x * hp[1024];
        acc[5] += a1.y * hp[1280];
        acc[6] += a1.z * hp[1536];
        acc[7] += a1.w * hp[1792];
    }
#pragma unroll
    for (int k = 0; k < 8; k++) {
        float v = acc[k] * sinv[k] + bias[k * 256 + t];
        g_g1[(size_t)n * 2048 + k * 256 + t] = fmaxf(v, 0.f);   // relu(g1)
    }
}

__global__ __launch_bounds__(256) void agg2_kernel(const int* __restrict__ src,
                                                   const float* __restrict__ bias)
{
    int n = blockIdx.x, t = threadIdx.x;
    float inv = g_inv2[n];
    float acc = 0.f;
    int s0 = g_rowstart[n], s1 = g_rowstart[n + 1];
    for (int ii = s0; ii < s1; ii++) {
        int e = g_csr[ii];
        acc += g_ebuf2[e] * g_h2[(size_t)src[e] * 256 + t];
    }
    // x2 -> cat1 cols [256,512)
    g_cat1[(size_t)n * 1024 + 256 + t] = acc * inv + bias[t];
}

// ---------------- projection to 4-D + squared norms ----------------
__global__ __launch_bounds__(256) void proj_kernel(const float* __restrict__ W_proj,
                                                   const float* __restrict__ b_proj)
{
    int gw = (blockIdx.x * 256 + threadIdx.x) >> 5;
    int l = threadIdx.x & 31;
    if (gw >= NN) return;
    const float* f = g_cat1 + (size_t)gw * 1024;
    float a0 = 0.f, a1 = 0.f, a2 = 0.f, a3 = 0.f;
    for (int j = l; j < 512; j += 32) {
        float v = f[j];
        float4 w = ((const float4*)W_proj)[j];
        a0 += v * w.x; a1 += v * w.y; a2 += v * w.z; a3 += v * w.w;
    }
#pragma unroll
    for (int off = 16; off; off >>= 1) {
        a0 += __shfl_down_sync(0xffffffffu, a0, off);
        a1 += __shfl_down_sync(0xffffffffu, a1, off);
        a2 += __shfl_down_sync(0xffffffffu, a2, off);
        a3 += __shfl_down_sync(0xffffffffu, a3, off);
    }
    if (l == 0) {
        a0 += b_proj[0]; a1 += b_proj[1]; a2 += b_proj[2]; a3 += b_proj[3];
        g_g4[gw] = make_float4(a0, a1, a2, a3);
        g_sq[gw] = a0 * a0 + a1 * a1 + a2 * a2 + a3 * a3;
    }
}

// ---------------- exact KNN via block-per-row radix select ----------------
// Shared layout (dynamic): uint32 keys[NN] (order-preserving float encoding).
// 4 MSB-first byte passes find the exact rank-(K-1) key; then collect the
// < keys plus index-sorted == keys. Output sorted by index -> deterministic.
__global__ __launch_bounds__(256) void knn_kernel()
{
    extern __shared__ unsigned int skey[];        // NN entries = 48 KB
    __shared__ int hist[256];
    __shared__ int list[KNN_K];
    __shared__ int eq[128];
    __shared__ int c_less, c_eq;
    __shared__ unsigned int s_prefix;
    __shared__ int s_rank;

    int row = blockIdx.x;
    int t = threadIdx.x;
    float4 gi = g_g4[row];
    float sqi = g_sq[row];

    // distances -> monotone uint keys (same formula as reference: sq+sq-2dot)
    for (int j = t; j < NN; j += 256) {
        float4 gj = g_g4[j];
        float d2 = sqi + g_sq[j]
                 - 2.f * (gi.x * gj.x + gi.y * gj.y + gi.z * gj.z + gi.w * gj.w);
        unsigned int u = __float_as_uint(d2);
        u = (u & 0x80000000u) ? ~u : (u | 0x80000000u);
        skey[j] = u;
    }
    if (t == 0) { s_prefix = 0u; s_rank = KNN_K - 1; c_less = 0; c_eq = 0; }
    __syncthreads();

    // 4 radix passes (MSB byte first)
    for (int shift = 24; shift >= 0; shift -= 8) {
        hist[t] = 0;
        __syncthreads();
        unsigned int prefix = s_prefix;
        unsigned int pmask = (shift == 24) ? 0u : (0xFFFFFFFFu << (shift + 8));
        for (int j = t; j < NN; j += 256) {
            unsigned int u = skey[j];
            if ((u & pmask) == prefix)
                atomicAdd(&hist[(u >> shift) & 0xFFu], 1);
        }
        __syncthreads();
        // inclusive Hillis-Steele scan over 256 bins
        for (int off = 1; off < 256; off <<= 1) {
            int add = (t >= off) ? hist[t - off] : 0;
            __syncthreads();
            hist[t] += add;
            __syncthreads();
        }
        int rank = s_rank;
        int before = (t == 0) ? 0 : hist[t - 1];
        if (before <= rank && rank < hist[t]) {         // exactly one thread
            s_prefix = prefix | ((unsigned int)t << shift);
            s_rank = rank - before;
        }
        __syncthreads();
    }

    unsigned int T = s_prefix;   // exact rank-(K-1) key
    for (int j = t; j < NN; j += 256) {
        unsigned int u = skey[j];
        if (u < T) {
            int p = atomicAdd(&c_less, 1);
            list[p] = j;                                 // c_less <= K-1 guaranteed
        } else if (u == T) {
            int p = atomicAdd(&c_eq, 1);
            if (p < 128) eq[p] = j;
        }
    }
    __syncthreads();

    if (t == 0) {
        int ne = c_eq < 128 ? c_eq : 128;
        int need = KNN_K - c_less;
        for (int a = 0; a < need; a++) {                 // usually need == 1
            int best = a;
            for (int b = a + 1; b < ne; b++)
                if (eq[b] < eq[best]) best = b;
            int tmp = eq[a]; eq[a] = eq[best]; eq[best] = tmp;
            list[c_less + a] = eq[a];
        }
    }
    __syncthreads();

    // rank-sort 50 distinct indices -> deterministic order
    if (t < KNN_K) {
        int myv = list[t];
        int r = 0;
#pragma unroll
        for (int j = 0; j < KNN_K; j++) r += (list[j] < myv);
        g_knn[row * KNN_K + r] = myv;
    }
}

// ---------------- sim = mean(final[idx]) -> LayerNorm -> cat1[512:1024) ----------------
__global__ __launch_bounds__(256) void simln_kernel(const float* __restrict__ ln_g,
                                                    const float* __restrict__ ln_b)
{
    __shared__ float red[256];
    int n = blockIdx.x, t = threadIdx.x;
    const int* ip = g_knn + n * KNN_K;
    float a0 = 0.f, a1 = 0.f;
    for (int kk = 0; kk < KNN_K; kk++) {
        const float* r = g_cat1 + (size_t)ip[kk] * 1024;
        a0 += r[t];
        a1 += r[t + 256];
    }
    a0 *= (1.f / 50.f);
    a1 *= (1.f / 50.f);
    red[t] = a0 + a1;
    __syncthreads();
    for (int s = 128; s; s >>= 1) { if (t < s) red[t] += red[t + s]; __syncthreads(); }
    float mu = red[0] * (1.f / 512.f);
    __syncthreads();
    float d0 = a0 - mu, d1 = a1 - mu;
    red[t] = d0 * d0 + d1 * d1;
    __syncthreads();
    for (int s = 128; s; s >>= 1) { if (t < s) red[t] += red[t + s]; __syncthreads(); }
    float var = red[0] * (1.f / 512.f);
    float rstd = rsqrtf(var + 1e-5f);
    float* o = g_cat1 + (size_t)n * 1024 + 512;
    o[t]       = d0 * rstd * ln_g[t]       + ln_b[t];
    o[t + 256] = d1 * rstd * ln_g[t + 256] + ln_b[t + 256];
}

// ---------------- final edge prediction ----------------
__global__ __launch_bounds__(256) void pred_node_kernel(const float* __restrict__ W_pred)
{
    int gw = (blockIdx.x * 256 + threadIdx.x) >> 5;
    int l = threadIdx.x & 31;
    if (gw >= NN) return;
    const float* hp = g_hh + (size_t)gw * 64;
    float a = 0.f, b = 0.f;
    for (int c = l; c < 64; c += 32) {
        float v = hp[c];
        a += v * W_pred[c];
        b += v * W_pred[64 + c];
    }
#pragma unroll
    for (int off = 16; off; off >>= 1) {
        a += __shfl_down_sync(0xffffffffu, a, off);
        b += __shfl_down_sync(0xffffffffu, b, off);
    }
    if (l == 0) { g_pd[gw] = a; g_pm[gw] = b; }
}

__global__ void pred_edge_kernel(const int* __restrict__ dis, const int* __restrict__ mir,
                                 const float* __restrict__ b_pred, float* __restrict__ out)
{
    int e = blockIdx.x * blockDim.x + threadIdx.x;
    if (e >= NE) return;
    float z = g_pd[dis[e]] + g_pm[mir[e]] + b_pred[0];
    out[e] = 1.f / (1.f + expf(-z));
}

// ---------------- host launcher ----------------
static inline void launch_sgemm(const float* A, int lda, const float* B, int ldb,
                                float* C, int ldc, int M, int K, int Nc,
                                const float* bias, int act)
{
    dim3 grid((Nc + 63) / 64, (M + 127) / 128);
    sgemm_kernel<<<grid, 256>>>(A, lda, B, ldb, C, ldc, M, K, Nc, bias, act);
}

extern "C" void kernel_launch(void* const* d_in, const int* in_sizes, int n_in,
                              void* d_out, int out_size)
{
    const float* d_sim    = (const float*)d_in[0];
    const float* m_sim    = (const float*)d_in[1];
    const int*   diseases = (const int*)d_in[2];
    const int*   mirnas   = (const int*)d_in[3];
    const float* W_dfc    = (const float*)d_in[4];
    const float* W_mfc    = (const float*)d_in[5];
    const float* W_lin1   = (const float*)d_in[6];
    const float* b_lin1   = (const float*)d_in[7];
    const float* W_gat1   = (const float*)d_in[8];
    const float* att_src1 = (const float*)d_in[9];
    const float* att_dst1 = (const float*)d_in[10];
    const float* b_gat1   = (const float*)d_in[11];
    const float* W_gat2   = (const float*)d_in[12];
    const float* att_src2 = (const float*)d_in[13];
    const float* att_dst2 = (const float*)d_in[14];
    const float* b_gat2   = (const float*)d_in[15];
    const float* W_proj   = (const float*)d_in[16];
    const float* b_proj   = (const float*)d_in[17];
    const float* ln_g     = (const float*)d_in[18];
    const float* ln_b     = (const float*)d_in[19];
    const float* W_lin    = (const float*)d_in[20];
    const float* b_lin    = (const float*)d_in[21];
    const float* W_dfc1   = (const float*)d_in[22];
    const float* b_dfc1   = (const float*)d_in[23];
    const float* W_mfc1   = (const float*)d_in[24];
    const float* b_mfc1   = (const float*)d_in[25];
    const float* W_pred   = (const float*)d_in[26];
    const float* b_pred   = (const float*)d_in[27];
    float* out = (float*)d_out;

    float *h1, *g1, *h2, *cat1, *cat2, *hh;
    cudaGetSymbolAddress((void**)&h1,   g_h1);
    cudaGetSymbolAddress((void**)&g1,   g_g1);
    cudaGetSymbolAddress((void**)&h2,   g_h2);
    cudaGetSymbolAddress((void**)&cat1, g_cat1);
    cudaGetSymbolAddress((void**)&cat2, g_cat2);
    cudaGetSymbolAddress((void**)&hh,   g_hh);

    // dynamic smem for knn keys (48 KB > 48K static limit boundary)
    static int knn_attr_set = 0;
    if (!knn_attr_set) {
        cudaFuncSetAttribute(knn_kernel, cudaFuncAttributeMaxDynamicSharedMemorySize,
                             NN * (int)sizeof(unsigned int));
        knn_attr_set = 1;
    }

    const int EB = (NE + 255) / 256;

    // 1-2: feats -> cat2 cols [64,128)
    launch_sgemm(d_sim, ND, W_dfc, 64, cat2 + 64, 128, ND, ND, 64, nullptr, 0);
    launch_sgemm(m_sim, NM, W_mfc, 64, cat2 + (size_t)ND * 128 + 64, 128, NM, NM, 64, nullptr, 0);

    // 3: x1 = relu(feats@W_lin1 + b) -> cat1 cols [0,256)
    launch_sgemm(cat2 + 64, 128, W_lin1, 256, cat1, 1024, NN, 64, 256, b_lin1, 1);

    // 4: h1 = feats@W_gat1
    launch_sgemm(cat2 + 64, 128, W_gat1, 2048, h1, 2048, NN, 64, 2048, nullptr, 0);

    // 5: init softmax/CSR buffers
    init_kernel<<<(NN * 8 + 255) / 256, 256>>>();

    // 6-8: CSR by dst
    deg_kernel<<<EB, 256>>>(mirnas);
    scan_kernel<<<1, 1024>>>();
    scatter_kernel<<<EB, 256>>>(mirnas);

    // 9-13: GAT1
    attn_node1_kernel<<<NN, 256>>>(att_src1, att_dst1);
    edge1_pass1<<<EB, 256>>>(diseases, mirnas);
    edge1_pass2<<<EB, 256>>>(mirnas);
    invden_kernel<<<(NN * 8 + 255) / 256, 256>>>(g_den1, g_inv1, NN * 8);
    agg1_kernel<<<NN, 256>>>(diseases, b_gat1);

    // 14: h2 = g1@W_gat2 (biggest GEMM)
    launch_sgemm(g1, 2048, W_gat2, 256, h2, 256, NN, 2048, 256, nullptr, 0);

    // 15-18: GAT2 -> x2 into cat1 cols [256,512)
    attn_node2_kernel<<<NN, 256>>>(att_src2, att_dst2);
    edge2_pass1<<<EB, 256>>>(diseases, mirnas);
    edge2_pass2<<<EB, 256>>>(mirnas);
    invden_kernel<<<(NN + 255) / 256, 256>>>(g_den2, g_inv2, NN);
    agg2_kernel<<<NN, 256>>>(diseases, b_gat2);

    // 19-21: KNN + sim + LN -> cat1 cols [512,1024)
    proj_kernel<<<NN / 8, 256>>>(W_proj, b_proj);
    knn_kernel<<<NN, 256, NN * sizeof(unsigned int)>>>();
    simln_kernel<<<NN, 256>>>(ln_g, ln_b);

    // 22: h = cat1@W_lin + b -> cat2 cols [0,64)
    launch_sgemm(cat1, 1024, W_lin, 64, cat2, 128, NN, 1024, 64, b_lin, 0);

    // 23-24: elu(fc1) -> hh
    launch_sgemm(cat2, 128, W_dfc1, 64, hh, 64, ND, 128, 64, b_dfc1, 2);
    launch_sgemm(cat2 + (size_t)ND * 128, 128, W_mfc1, 64, hh + (size_t)ND * 64, 64,
                 NM, 128, 64, b_mfc1, 2);

    // 25-26: prediction
    pred_node_kernel<<<(NN * 32 + 255) / 256, 256>>>(W_pred);
    pred_edge_kernel<<<EB, 256>>>(diseases, mirnas, b_pred, out);
}

// round 16
// speedup vs baseline: 21.2209x; 1.6359x over previous
#include <cuda_runtime.h>
#include <math.h>
#include <stdint.h>

#define ND 4096
#define NM 8192
#define NN 12288           // ND + NM
#define NE 262144
#define KNN_K 50
#define SPLITS 8

// ---------------- scratch (static __device__, no allocations) ----------------
__device__ float g_h1[(size_t)NN * 2048];     // GAT1 per-head features
__device__ float g_g1[(size_t)NN * 2048];     // relu(GAT1 out + b)
__device__ float g_h2[(size_t)NN * 256];      // GAT2 features
__device__ float g_cat1[(size_t)NN * 1024];   // [x1(256) | x2(256) | simLN(512)]
__device__ float g_cat2[(size_t)NN * 128];    // [h(64) | feats(64)]
__device__ float g_hh[(size_t)NN * 64];       // elu(fc1) output
__device__ float g_ebuf1[(size_t)NE * 8];     // GAT1 edge scores -> exp values
__device__ float g_ebuf2[NE];                 // GAT2 edge scores -> exp values
__device__ float g_asrc1[NN * 8], g_adst1[NN * 8];
__device__ float g_m1[NN * 8], g_den1[NN * 8], g_inv1[NN * 8];
__device__ float g_as2[NN], g_ad2[NN], g_m2[NN], g_den2[NN], g_inv2[NN];
__device__ float4 g_g4[NN];                   // 4-D projection for KNN
__device__ float g_sq[NN];
__device__ int   g_knn[NN * KNN_K];
__device__ int   g_deg[NN], g_rowstart[NN + 1], g_cursor[NN], g_csr[NE];
__device__ float g_pd[NN], g_pm[NN];
__device__ float g_part[(size_t)SPLITS * NM * 64];   // split-K partials (16.8 MB)

// ---------------- generic tiled SGEMM: C = act(A@B + bias) ----------------
__global__ __launch_bounds__(256) void sgemm_kernel(
    const float* __restrict__ A, int lda,
    const float* __restrict__ B, int ldb,
    float* __restrict__ C, int ldc,
    int M, int K, int Nc,
    const float* __restrict__ bias, int act)
{
    __shared__ float As[16][132];   // [k][m], padded
    __shared__ float Bs[16][68];    // [k][n], padded
    int bm = blockIdx.y * 128, bn = blockIdx.x * 64;
    int tid = threadIdx.x;
    int ty = tid >> 4, tx = tid & 15;
    float acc[8][4];
#pragma unroll
    for (int i = 0; i < 8; i++)
#pragma unroll
        for (int j = 0; j < 4; j++) acc[i][j] = 0.f;

    for (int k0 = 0; k0 < K; k0 += 16) {
#pragma unroll
        for (int i = 0; i < 8; i++) {
            int idx = tid + i * 256;
            int m = idx >> 4, kk = idx & 15;
            int gm = bm + m;
            As[kk][m] = (gm < M) ? A[(size_t)gm * lda + k0 + kk] : 0.f;
        }
#pragma unroll
        for (int i = 0; i < 4; i++) {
            int idx = tid + i * 256;
            int kk = idx >> 6, n = idx & 63;
            int gn = bn + n;
            Bs[kk][n] = (gn < Nc) ? B[(size_t)(k0 + kk) * ldb + gn] : 0.f;
        }
        __syncthreads();
#pragma unroll
        for (int kk = 0; kk < 16; kk++) {
            float4 a0 = *(const float4*)&As[kk][ty * 8];
            float4 a1 = *(const float4*)&As[kk][ty * 8 + 4];
            float4 b4 = *(const float4*)&Bs[kk][tx * 4];
            float av[8] = {a0.x, a0.y, a0.z, a0.w, a1.x, a1.y, a1.z, a1.w};
            float bv[4] = {b4.x, b4.y, b4.z, b4.w};
#pragma unroll
            for (int i = 0; i < 8; i++)
#pragma unroll
                for (int j = 0; j < 4; j++) acc[i][j] += av[i] * bv[j];
        }
        __syncthreads();
    }
#pragma unroll
    for (int i = 0; i < 8; i++) {
        int gm = bm + ty * 8 + i;
        if (gm >= M) continue;
#pragma unroll
        for (int j = 0; j < 4; j++) {
            int gn = bn + tx * 4 + j;
            if (gn >= Nc) continue;
            float v = acc[i][j];
            if (bias) v += bias[gn];
            if (act == 1) v = fmaxf(v, 0.f);
            else if (act == 2) v = (v > 0.f) ? v : expm1f(v);
            C[(size_t)gm * ldc + gn] = v;
        }
    }
}

// ---------------- split-K GEMM for Nc=64 (feats GEMMs) ----------------
// partial[slice][row][64] += A[row, kbeg:kend] @ B[kbeg:kend, :64]
__global__ __launch_bounds__(256) void gemm64_splitk_kernel(
    const float* __restrict__ A, int lda,
    const float* __restrict__ B,          // ldb = 64
    float* __restrict__ part, int M, int K)
{
    __shared__ float As[16][132];
    __shared__ float Bs[16][68];
    int slice = blockIdx.x;
    int bm = blockIdx.y * 128;
    int klen = K / SPLITS;
    int kbeg = slice * klen;
    int tid = threadIdx.x;
    int ty = tid >> 4, tx = tid & 15;
    float acc[8][4];
#pragma unroll
    for (int i = 0; i < 8; i++)
#pragma unroll
        for (int j = 0; j < 4; j++) acc[i][j] = 0.f;

    for (int k0 = kbeg; k0 < kbeg + klen; k0 += 16) {
#pragma unroll
        for (int i = 0; i < 8; i++) {
            int idx = tid + i * 256;
            int m = idx >> 4, kk = idx & 15;
            As[kk][m] = A[(size_t)(bm + m) * lda + k0 + kk];
        }
#pragma unroll
        for (int i = 0; i < 4; i++) {
            int idx = tid + i * 256;
            int kk = idx >> 6, n = idx & 63;
            Bs[kk][n] = B[(size_t)(k0 + kk) * 64 + n];
        }
        __syncthreads();
#pragma unroll
        for (int kk = 0; kk < 16; kk++) {
            float4 a0 = *(const float4*)&As[kk][ty * 8];
            float4 a1 = *(const float4*)&As[kk][ty * 8 + 4];
            float4 b4 = *(const float4*)&Bs[kk][tx * 4];
            float av[8] = {a0.x, a0.y, a0.z, a0.w, a1.x, a1.y, a1.z, a1.w};
            float bv[4] = {b4.x, b4.y, b4.z, b4.w};
#pragma unroll
            for (int i = 0; i < 8; i++)
#pragma unroll
                for (int j = 0; j < 4; j++) acc[i][j] += av[i] * bv[j];
        }
        __syncthreads();
    }
    float* op = part + ((size_t)slice * M + bm) * 64;
#pragma unroll
    for (int i = 0; i < 8; i++) {
        int m = ty * 8 + i;
#pragma unroll
        for (int j = 0; j < 4; j++)
            op[(size_t)m * 64 + tx * 4 + j] = acc[i][j];
    }
}

// deterministic reduce: C[row*ldc + c] = sum_s part[s][row][c]
__global__ void reduce64_kernel(const float* __restrict__ part, int M,
                                float* __restrict__ C, int ldc)
{
    int i = blockIdx.x * blockDim.x + threadIdx.x;
    if (i >= M * 64) return;
    int row = i >> 6, c = i & 63;
    float s = 0.f;
#pragma unroll
    for (int sl = 0; sl < SPLITS; sl++)
        s += part[((size_t)sl * M + row) * 64 + c];
    C[(size_t)row * ldc + c] = s;
}

// ---------------- init ----------------
__global__ void init_kernel()
{
    int i = blockIdx.x * blockDim.x + threadIdx.x;
    if (i < NN * 8) { g_m1[i] = -INFINITY; g_den1[i] = 0.f; }
    if (i < NN)     { g_m2[i] = -INFINITY; g_den2[i] = 0.f; g_deg[i] = 0; g_cursor[i] = 0; }
}

// ---------------- CSR build over dst ----------------
__global__ void deg_kernel(const int* __restrict__ dst)
{
    int e = blockIdx.x * blockDim.x + threadIdx.x;
    if (e < NE) atomicAdd(&g_deg[dst[e]], 1);
}

__global__ __launch_bounds__(1024) void scan_kernel()
{
    __shared__ int ps[1024];
    int t = threadIdx.x;
    int base = t * 12;
    int loc[12]; int s = 0;
#pragma unroll
    for (int i = 0; i < 12; i++) { int v = g_deg[base + i]; loc[i] = s; s += v; }
    ps[t] = s;
    __syncthreads();
    for (int off = 1; off < 1024; off <<= 1) {
        int v = ps[t];
        int add = (t >= off) ? ps[t - off] : 0;
        __syncthreads();
        ps[t] = v + add;
        __syncthreads();
    }
    int prev = (t == 0) ? 0 : ps[t - 1];
#pragma unroll
    for (int i = 0; i < 12; i++) g_rowstart[base + i] = prev + loc[i];
    if (t == 1023) g_rowstart[NN] = ps[1023];
}

__global__ void scatter_kernel(const int* __restrict__ dst)
{
    int e = blockIdx.x * blockDim.x + threadIdx.x;
    if (e >= NE) return;
    int d = dst[e];
    int p = atomicAdd(&g_cursor[d], 1);
    g_csr[g_rowstart[d] + p] = e;
}

// ---------------- attention node scores ----------------
__global__ __launch_bounds__(256) void attn_node1_kernel(
    const float* __restrict__ att_src, const float* __restrict__ att_dst)
{
    int n = blockIdx.x;
    int t = threadIdx.x, w = t >> 5, l = t & 31;
    const float* hp = g_h1 + (size_t)n * 2048 + w * 256;
    const float* as = att_src + w * 256;
    const float* ad = att_dst + w * 256;
    float s = 0.f, d = 0.f;
    for (int c = l; c < 256; c += 32) { float v = hp[c]; s += v * as[c]; d += v * ad[c]; }
#pragma unroll
    for (int off = 16; off; off >>= 1) {
        s += __shfl_down_sync(0xffffffffu, s, off);
        d += __shfl_down_sync(0xffffffffu, d, off);
    }
    if (l == 0) { g_asrc1[n * 8 + w] = s; g_adst1[n * 8 + w] = d; }
}

__global__ __launch_bounds__(256) void attn_node2_kernel(
    const float* __restrict__ att_src, const float* __restrict__ att_dst)
{
    __shared__ float ss[256], sd[256];
    int n = blockIdx.x, t = threadIdx.x;
    float v = g_h2[(size_t)n * 256 + t];
    ss[t] = v * att_src[t];
    sd[t] = v * att_dst[t];
    __syncthreads();
    for (int s = 128; s; s >>= 1) {
        if (t < s) { ss[t] += ss[t + s]; sd[t] += sd[t + s]; }
        __syncthreads();
    }
    if (t == 0) { g_as2[n] = ss[0]; g_ad2[n] = sd[0]; }
}

// ---------------- edge softmax passes ----------------
__device__ __forceinline__ void atomicMaxF(float* addr, float val)
{
    int* ia = (int*)addr;
    int old = *ia;
    while (__int_as_float(old) < val) {
        int assumed = old;
        old = atomicCAS(ia, assumed, __float_as_int(val));
        if (old == assumed) break;
    }
}

__global__ void edge1_pass1(const int* __restrict__ src, const int* __restrict__ dst)
{
    int e = blockIdx.x * blockDim.x + threadIdx.x;
    if (e >= NE) return;
    int s = src[e], d = dst[e];
#pragma unroll
    for (int h = 0; h < 8; h++) {
        float v = g_asrc1[s * 8 + h] + g_adst1[d * 8 + h];
        v = (v >= 0.f) ? v : 0.2f * v;
        g_ebuf1[(size_t)e * 8 + h] = v;
        atomicMaxF(&g_m1[d * 8 + h], v);
    }
}

__global__ void edge1_pass2(const int* __restrict__ dst)
{
    int e = blockIdx.x * blockDim.x + threadIdx.x;
    if (e >= NE) return;
    int d = dst[e];
#pragma unroll
    for (int h = 0; h < 8; h++) {
        float m = g_m1[d * 8 + h];
        if (!isfinite(m)) m = 0.f;
        float ex = expf(g_ebuf1[(size_t)e * 8 + h] - m);
        g_ebuf1[(size_t)e * 8 + h] = ex;
        atomicAdd(&g_den1[d * 8 + h], ex);
    }
}

__global__ void edge2_pass1(const int* __restrict__ src, const int* __restrict__ dst)
{
    int e = blockIdx.x * blockDim.x + threadIdx.x;
    if (e >= NE) return;
    float v = g_as2[src[e]] + g_ad2[dst[e]];
    v = (v >= 0.f) ? v : 0.2f * v;
    g_ebuf2[e] = v;
    atomicMaxF(&g_m2[dst[e]], v);
}

__global__ void edge2_pass2(const int* __restrict__ dst)
{
    int e = blockIdx.x * blockDim.x + threadIdx.x;
    if (e >= NE) return;
    int d = dst[e];
    float m = g_m2[d];
    if (!isfinite(m)) m = 0.f;
    float ex = expf(g_ebuf2[e] - m);
    g_ebuf2[e] = ex;
    atomicAdd(&g_den2[d], ex);
}

__global__ void invden_kernel(const float* __restrict__ den, float* __restrict__ inv, int count)
{
    int i = blockIdx.x * blockDim.x + threadIdx.x;
    if (i < count) inv[i] = 1.f / fmaxf(den[i], 1e-16f);
}

// ---------------- GAT aggregations (CSR, no atomics) ----------------
__global__ __launch_bounds__(256) void agg1_kernel(const int* __restrict__ src,
                                                   const float* __restrict__ bias)
{
    int n = blockIdx.x, t = threadIdx.x;
    __shared__ float sinv[8];
    if (t < 8) sinv[t] = g_inv1[n * 8 + t];
    __syncthreads();
    float acc[8];
#pragma unroll
    for (int k = 0; k < 8; k++) acc[k] = 0.f;
    int s0 = g_rowstart[n], s1 = g_rowstart[n + 1];
    for (int ii = s0; ii < s1; ii++) {
        int e = g_csr[ii];
        int sNode = src[e];
        const float* hp = g_h1 + (size_t)sNode * 2048 + t;
        const float4* ap = (const float4*)(g_ebuf1 + (size_t)e * 8);
        float4 a0 = ap[0], a1 = ap[1];
        acc[0] += a0.x * hp[0];
        acc[1] += a0.y * hp[256];
        acc[2] += a0.z * hp[512];
        acc[3] += a0.w * hp[768];
        acc[4] += a1.x * hp[1024];
        acc[5] += a1.y * hp[1280];
        acc[6] += a1.z * hp[1536];
        acc[7] += a1.w * hp[1792];
    }
#pragma unroll
    for (int k = 0; k < 8; k++) {
        float v = acc[k] * sinv[k] + bias[k * 256 + t];
        g_g1[(size_t)n * 2048 + k * 256 + t] = fmaxf(v, 0.f);   // relu(g1)
    }
}

__global__ __launch_bounds__(256) void agg2_kernel(const int* __restrict__ src,
                                                   const float* __restrict__ bias)
{
    int n = blockIdx.x, t = threadIdx.x;
    float inv = g_inv2[n];
    float acc = 0.f;
    int s0 = g_rowstart[n], s1 = g_rowstart[n + 1];
    for (int ii = s0; ii < s1; ii++) {
        int e = g_csr[ii];
        acc += g_ebuf2[e] * g_h2[(size_t)src[e] * 256 + t];
    }
    g_cat1[(size_t)n * 1024 + 256 + t] = acc * inv + bias[t];
}

// ---------------- projection to 4-D + squared norms ----------------
__global__ __launch_bounds__(256) void proj_kernel(const float* __restrict__ W_proj,
                                                   const float* __restrict__ b_proj)
{
    int gw = (blockIdx.x * 256 + threadIdx.x) >> 5;
    int l = threadIdx.x & 31;
    if (gw >= NN) return;
    const float* f = g_cat1 + (size_t)gw * 1024;
    float a0 = 0.f, a1 = 0.f, a2 = 0.f, a3 = 0.f;
    for (int j = l; j < 512; j += 32) {
        float v = f[j];
        float4 w = ((const float4*)W_proj)[j];
        a0 += v * w.x; a1 += v * w.y; a2 += v * w.z; a3 += v * w.w;
    }
#pragma unroll
    for (int off = 16; off; off >>= 1) {
        a0 += __shfl_down_sync(0xffffffffu, a0, off);
        a1 += __shfl_down_sync(0xffffffffu, a1, off);
        a2 += __shfl_down_sync(0xffffffffu, a2, off);
        a3 += __shfl_down_sync(0xffffffffu, a3, off);
    }
    if (l == 0) {
        a0 += b_proj[0]; a1 += b_proj[1]; a2 += b_proj[2]; a3 += b_proj[3];
        g_g4[gw] = make_float4(a0, a1, a2, a3);
        g_sq[gw] = a0 * a0 + a1 * a1 + a2 * a2 + a3 * a3;
    }
}

// ---------------- exact KNN via block-per-row radix select ----------------
// Histogram atomics are warp-aggregated via __match_any_sync: the MSB pass
// concentrates keys in 1-2 bins, which would serialize 12K lane-atomics/block.
__global__ __launch_bounds__(256) void knn_kernel()
{
    extern __shared__ unsigned int skey[];        // NN entries = 48 KB
    __shared__ int hist[256];
    __shared__ int list[KNN_K];
    __shared__ int eq[128];
    __shared__ int c_less, c_eq;
    __shared__ unsigned int s_prefix;
    __shared__ int s_rank;

    int row = blockIdx.x;
    int t = threadIdx.x;
    int lane = t & 31;
    float4 gi = g_g4[row];
    float sqi = g_sq[row];

    // distances -> monotone uint keys (same formula as reference: sq+sq-2dot)
    for (int j = t; j < NN; j += 256) {
        float4 gj = g_g4[j];
        float d2 = sqi + g_sq[j]
                 - 2.f * (gi.x * gj.x + gi.y * gj.y + gi.z * gj.z + gi.w * gj.w);
        unsigned int u = __float_as_uint(d2);
        u = (u & 0x80000000u) ? ~u : (u | 0x80000000u);
        skey[j] = u;
    }
    if (t == 0) { s_prefix = 0u; s_rank = KNN_K - 1; c_less = 0; c_eq = 0; }
    __syncthreads();

    // 4 radix passes (MSB byte first), warp-aggregated histogram atomics
    for (int shift = 24; shift >= 0; shift -= 8) {
        hist[t] = 0;
        __syncthreads();
        unsigned int prefix = s_prefix;
        unsigned int pmask = (shift == 24) ? 0u : (0xFFFFFFFFu << (shift + 8));
        for (int j = t; j < NN; j += 256) {       // NN % 256 == 0: warp uniform
            unsigned int u = skey[j];
            int bin = ((u & pmask) == prefix) ? (int)((u >> shift) & 0xFFu) : -1;
            unsigned int msk = __match_any_sync(0xffffffffu, bin);
            if (bin >= 0 && (msk & ((1u << lane) - 1u)) == 0u)   // lowest lane of group
                atomicAdd(&hist[bin], (int)__popc(msk));
        }
        __syncthreads();
        // inclusive Hillis-Steele scan over 256 bins
        for (int off = 1; off < 256; off <<= 1) {
            int add = (t >= off) ? hist[t - off] : 0;
            __syncthreads();
            hist[t] += add;
            __syncthreads();
        }
        int rank = s_rank;
        int before = (t == 0) ? 0 : hist[t - 1];
        if (before <= rank && rank < hist[t]) {         // exactly one thread
            s_prefix = prefix | ((unsigned int)t << shift);
            s_rank = rank - before;
        }
        __syncthreads();
    }

    unsigned int T = s_prefix;   // exact rank-(K-1) key
    for (int j = t; j < NN; j += 256) {
        unsigned int u = skey[j];
        if (u < T) {
            int p = atomicAdd(&c_less, 1);
            list[p] = j;                                 // c_less <= K-1 guaranteed
        } else if (u == T) {
            int p = atomicAdd(&c_eq, 1);
            if (p < 128) eq[p] = j;
        }
    }
    __syncthreads();

    if (t == 0) {
        int ne = c_eq < 128 ? c_eq : 128;
        int need = KNN_K - c_less;
        for (int a = 0; a < need; a++) {                 // usually need == 1
            int best = a;
            for (int b = a + 1; b < ne; b++)
                if (eq[b] < eq[best]) best = b;
            int tmp = eq[a]; eq[a] = eq[best]; eq[best] = tmp;
            list[c_less + a] = eq[a];
        }
    }
    __syncthreads();

    // rank-sort 50 distinct indices -> deterministic order
    if (t < KNN_K) {
        int myv = list[t];
        int r = 0;
#pragma unroll
        for (int j = 0; j < KNN_K; j++) r += (list[j] < myv);
        g_knn[row * KNN_K + r] = myv;
    }
}

// ---------------- sim = mean(final[idx]) -> LayerNorm -> cat1[512:1024) ----------------
__global__ __launch_bounds__(256) void simln_kernel(const float* __restrict__ ln_g,
                                                    const float* __restrict__ ln_b)
{
    __shared__ float red[256];
    int n = blockIdx.x, t = threadIdx.x;
    const int* ip = g_knn + n * KNN_K;
    float a0 = 0.f, a1 = 0.f;
    for (int kk = 0; kk < KNN_K; kk++) {
        const float* r = g_cat1 + (size_t)ip[kk] * 1024;
        a0 += r[t];
        a1 += r[t + 256];
    }
    a0 *= (1.f / 50.f);
    a1 *= (1.f / 50.f);
    red[t] = a0 + a1;
    __syncthreads();
    for (int s = 128; s; s >>= 1) { if (t < s) red[t] += red[t + s]; __syncthreads(); }
    float mu = red[0] * (1.f / 512.f);
    __syncthreads();
    float d0 = a0 - mu, d1 = a1 - mu;
    red[t] = d0 * d0 + d1 * d1;
    __syncthreads();
    for (int s = 128; s; s >>= 1) { if (t < s) red[t] += red[t + s]; __syncthreads(); }
    float var = red[0] * (1.f / 512.f);
    float rstd = rsqrtf(var + 1e-5f);
    float* o = g_cat1 + (size_t)n * 1024 + 512;
    o[t]       = d0 * rstd * ln_g[t]       + ln_b[t];
    o[t + 256] = d1 * rstd * ln_g[t + 256] + ln_b[t + 256];
}

// ---------------- final edge prediction ----------------
__global__ __launch_bounds__(256) void pred_node_kernel(const float* __restrict__ W_pred)
{
    int gw = (blockIdx.x * 256 + threadIdx.x) >> 5;
    int l = threadIdx.x & 31;
    if (gw >= NN) return;
    const float* hp = g_hh + (size_t)gw * 64;
    float a = 0.f, b = 0.f;
    for (int c = l; c < 64; c += 32) {
        float v = hp[c];
        a += v * W_pred[c];
        b += v * W_pred[64 + c];
    }
#pragma unroll
    for (int off = 16; off; off >>= 1) {
        a += __shfl_down_sync(0xffffffffu, a, off);
        b += __shfl_down_sync(0xffffffffu, b, off);
    }
    if (l == 0) { g_pd[gw] = a; g_pm[gw] = b; }
}

__global__ void pred_edge_kernel(const int* __restrict__ dis, const int* __restrict__ mir,
                                 const float* __restrict__ b_pred, float* __restrict__ out)
{
    int e = blockIdx.x * blockDim.x + threadIdx.x;
    if (e >= NE) return;
    float z = g_pd[dis[e]] + g_pm[mir[e]] + b_pred[0];
    out[e] = 1.f / (1.f + expf(-z));
}

// ---------------- host launcher ----------------
static inline void launch_sgemm(const float* A, int lda, const float* B, int ldb,
                                float* C, int ldc, int M, int K, int Nc,
                                const float* bias, int act)
{
    dim3 grid((Nc + 63) / 64, (M + 127) / 128);
    sgemm_kernel<<<grid, 256>>>(A, lda, B, ldb, C, ldc, M, K, Nc, bias, act);
}

extern "C" void kernel_launch(void* const* d_in, const int* in_sizes, int n_in,
                              void* d_out, int out_size)
{
    const float* d_sim    = (const float*)d_in[0];
    const float* m_sim    = (const float*)d_in[1];
    const int*   diseases = (const int*)d_in[2];
    const int*   mirnas   = (const int*)d_in[3];
    const float* W_dfc    = (const float*)d_in[4];
    const float* W_mfc    = (const float*)d_in[5];
    const float* W_lin1   = (const float*)d_in[6];
    const float* b_lin1   = (const float*)d_in[7];
    const float* W_gat1   = (const float*)d_in[8];
    const float* att_src1 = (const float*)d_in[9];
    const float* att_dst1 = (const float*)d_in[10];
    const float* b_gat1   = (const float*)d_in[11];
    const float* W_gat2   = (const float*)d_in[12];
    const float* att_src2 = (const float*)d_in[13];
    const float* att_dst2 = (const float*)d_in[14];
    const float* b_gat2   = (const float*)d_in[15];
    const float* W_proj   = (const float*)d_in[16];
    const float* b_proj   = (const float*)d_in[17];
    const float* ln_g     = (const float*)d_in[18];
    const float* ln_b     = (const float*)d_in[19];
    const float* W_lin    = (const float*)d_in[20];
    const float* b_lin    = (const float*)d_in[21];
    const float* W_dfc1   = (const float*)d_in[22];
    const float* b_dfc1   = (const float*)d_in[23];
    const float* W_mfc1   = (const float*)d_in[24];
    const float* b_mfc1   = (const float*)d_in[25];
    const float* W_pred   = (const float*)d_in[26];
    const float* b_pred   = (const float*)d_in[27];
    float* out = (float*)d_out;

    float *h1, *g1, *h2, *cat1, *cat2, *hh, *part;
    cudaGetSymbolAddress((void**)&h1,   g_h1);
    cudaGetSymbolAddress((void**)&g1,   g_g1);
    cudaGetSymbolAddress((void**)&h2,   g_h2);
    cudaGetSymbolAddress((void**)&cat1, g_cat1);
    cudaGetSymbolAddress((void**)&cat2, g_cat2);
    cudaGetSymbolAddress((void**)&hh,   g_hh);
    cudaGetSymbolAddress((void**)&part, g_part);

    static int knn_attr_set = 0;
    if (!knn_attr_set) {
        cudaFuncSetAttribute(knn_kernel, cudaFuncAttributeMaxDynamicSharedMemorySize,
                             NN * (int)sizeof(unsigned int));
        knn_attr_set = 1;
    }

    const int EB = (NE + 255) / 256;

    // 1-2: feats -> cat2 cols [64,128), split-K for full-chip occupancy
    {
        dim3 gd(SPLITS, ND / 128);
        gemm64_splitk_kernel<<<gd, 256>>>(d_sim, ND, W_dfc, part, ND, ND);
        reduce64_kernel<<<(ND * 64 + 255) / 256, 256>>>(part, ND, cat2 + 64, 128);
        dim3 gm(SPLITS, NM / 128);
        gemm64_splitk_kernel<<<gm, 256>>>(m_sim, NM, W_mfc, part, NM, NM);
        reduce64_kernel<<<(NM * 64 + 255) / 256, 256>>>(part, NM,
                                                        cat2 + (size_t)ND * 128 + 64, 128);
    }

    // 3: x1 = relu(feats@W_lin1 + b) -> cat1 cols [0,256)
    launch_sgemm(cat2 + 64, 128, W_lin1, 256, cat1, 1024, NN, 64, 256, b_lin1, 1);

    // 4: h1 = feats@W_gat1
    launch_sgemm(cat2 + 64, 128, W_gat1, 2048, h1, 2048, NN, 64, 2048, nullptr, 0);

    // 5: init softmax/CSR buffers
    init_kernel<<<(NN * 8 + 255) / 256, 256>>>();

    // 6-8: CSR by dst
    deg_kernel<<<EB, 256>>>(mirnas);
    scan_kernel<<<1, 1024>>>();
    scatter_kernel<<<EB, 256>>>(mirnas);

    // 9-13: GAT1
    attn_node1_kernel<<<NN, 256>>>(att_src1, att_dst1);
    edge1_pass1<<<EB, 256>>>(diseases, mirnas);
    edge1_pass2<<<EB, 256>>>(mirnas);
    invden_kernel<<<(NN * 8 + 255) / 256, 256>>>(g_den1, g_inv1, NN * 8);
    agg1_kernel<<<NN, 256>>>(diseases, b_gat1);

    // 14: h2 = g1@W_gat2 (biggest GEMM)
    launch_sgemm(g1, 2048, W_gat2, 256, h2, 256, NN, 2048, 256, nullptr, 0);

    // 15-18: GAT2 -> x2 into cat1 cols [256,512)
    attn_node2_kernel<<<NN, 256>>>(att_src2, att_dst2);
    edge2_pass1<<<EB, 256>>>(diseases, mirnas);
    edge2_pass2<<<EB, 256>>>(mirnas);
    invden_kernel<<<(NN + 255) / 256, 256>>>(g_den2, g_inv2, NN);
    agg2_kernel<<<NN, 256>>>(diseases, b_gat2);

    // 19-21: KNN + sim + LN -> cat1 cols [512,1024)
    proj_kernel<<<NN / 8, 256>>>(W_proj, b_proj);
    knn_kernel<<<NN, 256, NN * sizeof(unsigned int)>>>();
    simln_kernel<<<NN, 256>>>(ln_g, ln_b);

    // 22: h = cat1@W_lin + b -> cat2 cols [0,64)
    launch_sgemm(cat1, 1024, W_lin, 64, cat2, 128, NN, 1024, 64, b_lin, 0);

    // 23-24: elu(fc1) -> hh
    launch_sgemm(cat2, 128, W_dfc1, 64, hh, 64, ND, 128, 64, b_dfc1, 2);
    launch_sgemm(cat2 + (size_t)ND * 128, 128, W_mfc1, 64, hh + (size_t)ND * 64, 64,
                 NM, 128, 64, b_mfc1, 2);

    // 25-26: prediction
    pred_node_kernel<<<(NN * 32 + 255) / 256, 256>>>(W_pred);
    pred_edge_kernel<<<EB, 256>>>(diseases, mirnas, b_pred, out);
}